// round 12
// baseline (speedup 1.0000x reference)
#include <cuda_runtime.h>
#include <cuda_fp16.h>
#include <cstdint>

// Problem constants (fixed by setup_inputs)
#define BQ   4
#define NLYR 2
#define NP   100
#define NTOK 60
#define NTOT 6000
#define DD   768
#define NTAB 10

#define MT   47          // m tiles of 128 (6016 >= 6000)
#define NT   6           // n tiles of 256 (1536)
#define NS64 12          // k slabs of 64
#define AT64 16384       // 128 rows x 64 k fp16 = 16KB
#define BT64 32768       // 256 rows x 64 k fp16 = 32KB
#define STG64 49152      // stage: A + B = 48KB

#define KSPLIT 8

// ---------------- scratch ---------------------------------------------------
__device__ float g_G[DD * 2 * DD];
__device__ float g_Gp[KSPLIT * DD * 2 * DD];
__device__ float g_cp[BQ * DD];
__device__ float g_bias[BQ * 2 * DD];          // [c_t | u] per batch
__device__ float g_Y[(size_t)BQ * NTOT * 2 * DD];   // raw (no bias)
__device__ float g_tmax[BQ * NTAB * NTOK * DD];     // includes +c_t
__device__ float g_p2[BQ * NTAB * NTOK * DD];
__device__ float g_p2p[KSPLIT * BQ * NTAB * NTOK * DD];
// pre-swizzled fp16 tile images (SW128, 128B rows, 64-k slabs)
__device__ unsigned char g_Qh[(size_t)BQ * MT * NS64 * AT64];
__device__ unsigned char g_Wh[(size_t)BQ * NT * NS64 * BT64];

// ---------------- PTX helpers ----------------------------------------------
__device__ __forceinline__ uint32_t smem_u32(const void* p) {
    uint32_t a;
    asm("{ .reg .u64 t; cvta.to.shared.u64 t, %1; cvt.u32.u64 %0, t; }" : "=r"(a) : "l"(p));
    return a;
}
__device__ __forceinline__ void ldm_x4(uint32_t* r, uint32_t addr) {
    asm volatile("ldmatrix.sync.aligned.m8n8.x4.shared.b16 {%0,%1,%2,%3}, [%4];"
                 : "=r"(r[0]), "=r"(r[1]), "=r"(r[2]), "=r"(r[3]) : "r"(addr));
}
__device__ __forceinline__ void mma16816(float* d, const uint32_t* a,
                                         uint32_t b0, uint32_t b1) {
    asm volatile(
        "mma.sync.aligned.m16n8k16.row.col.f32.f16.f16.f32 "
        "{%0,%1,%2,%3}, {%4,%5,%6,%7}, {%8,%9}, {%0,%1,%2,%3};"
        : "+f"(d[0]), "+f"(d[1]), "+f"(d[2]), "+f"(d[3])
        : "r"(a[0]), "r"(a[1]), "r"(a[2]), "r"(a[3]), "r"(b0), "r"(b1));
}
__device__ __forceinline__ uint32_t ldm_addr128(uint32_t tilebase, int row0, int k0, int lane) {
    int row = row0 + (lane & 15);
    int kc  = k0 + ((lane >> 4) << 3);
    uint32_t off = (uint32_t)(row * 128 + kc * 2);
    off ^= (off >> 3) & 0x70;
    return tilebase + off;
}
__device__ __forceinline__ uint32_t swz128(uint32_t off) {
    return off ^ ((off >> 3) & 0x70);
}
// ---- bulk-copy (TMA engine, non-tensor) + mbarrier ----
__device__ __forceinline__ void mbar_init(uint32_t mb, uint32_t cnt) {
    asm volatile("mbarrier.init.shared.b64 [%0], %1;" :: "r"(mb), "r"(cnt) : "memory");
}
__device__ __forceinline__ void mbar_expect(uint32_t mb, uint32_t bytes) {
    asm volatile("mbarrier.arrive.expect_tx.shared.b64 _, [%0], %1;"
                 :: "r"(mb), "r"(bytes) : "memory");
}
__device__ __forceinline__ void mbar_arrive(uint32_t mb) {
    asm volatile("mbarrier.arrive.shared.b64 _, [%0];" :: "r"(mb) : "memory");
}
__device__ __forceinline__ void bulkcp(uint32_t dst, const void* src, uint32_t bytes, uint32_t mb) {
    asm volatile("cp.async.bulk.shared::cluster.global.mbarrier::complete_tx::bytes "
                 "[%0], [%1], %2, [%3];"
                 :: "r"(dst), "l"(src), "r"(bytes), "r"(mb) : "memory");
}
__device__ __forceinline__ void mbar_wait(uint32_t mb, uint32_t parity) {
    asm volatile(
        "{\n\t.reg .pred P1;\n\t"
        "WAITLP_%=:\n\t"
        "mbarrier.try_wait.parity.acquire.cta.shared::cta.b64 P1, [%0], %1, 0x989680;\n\t"
        "@P1 bra.uni WAITDN_%=;\n\t"
        "bra.uni WAITLP_%=;\n\t"
        "WAITDN_%=:\n\t}"
        :: "r"(mb), "r"(parity) : "memory");
}

// ---------------- SIMT GEMM with split-K (small ops) -------------------------
__global__ __launch_bounds__(256)
void gemm_k(const float* __restrict__ A, long a_rs, long a_bs,
            const float* __restrict__ Bm, long b_ns, long b_ks, long b_bs,
            float* __restrict__ C, long c_ld, long c_bs, long c_ss,
            int M, int N, int K, int nsplit)
{
    const int BM = 128, BN = 128, BK = 16;
    __shared__ float As[BK][BM + 4];
    __shared__ float Bs[BK][BN + 4];
    int bz = blockIdx.z / nsplit;
    int sp = blockIdx.z % nsplit;
    int klen = K / nsplit;
    int kbeg = sp * klen;
    const float* Ab = A  + (long)bz * a_bs;
    const float* Bb = Bm + (long)bz * b_bs;
    float*       Cb = C  + (long)bz * c_bs + (long)sp * c_ss;
    int m0 = blockIdx.y * BM, n0 = blockIdx.x * BN;
    int tid = threadIdx.x, tx = tid & 15, ty = tid >> 4;
    float acc[8][8];
    #pragma unroll
    for (int i = 0; i < 8; i++)
        #pragma unroll
        for (int j = 0; j < 8; j++) acc[i][j] = 0.f;
    for (int k0 = kbeg; k0 < kbeg + klen; k0 += BK) {
        #pragma unroll
        for (int i = 0; i < 8; i++) {
            int e = tid + i * 256, m = e >> 4, k = e & 15;
            float v = 0.f;
            if (m0 + m < M) v = Ab[(long)(m0 + m) * a_rs + (k0 + k)];
            As[k][m] = v;
        }
        if (b_ks == 1) {
            #pragma unroll
            for (int i = 0; i < 8; i++) {
                int e = tid + i * 256, n = e >> 4, k = e & 15;
                Bs[k][n] = Bb[(long)(n0 + n) * b_ns + (long)(k0 + k) * b_ks];
            }
        } else {
            #pragma unroll
            for (int i = 0; i < 8; i++) {
                int e = tid + i * 256, k = e >> 7, n = e & 127;
                Bs[k][n] = Bb[(long)(n0 + n) * b_ns + (long)(k0 + k) * b_ks];
            }
        }
        __syncthreads();
        #pragma unroll
        for (int kk = 0; kk < BK; kk++) {
            float a[8], bb[8];
            #pragma unroll
            for (int i = 0; i < 8; i++) a[i]  = As[kk][ty * 8 + i];
            #pragma unroll
            for (int j = 0; j < 8; j++) bb[j] = Bs[kk][tx * 8 + j];
            #pragma unroll
            for (int i = 0; i < 8; i++)
                #pragma unroll
                for (int j = 0; j < 8; j++) acc[i][j] += a[i] * bb[j];
        }
        __syncthreads();
    }
    #pragma unroll
    for (int i = 0; i < 8; i++) {
        int m = m0 + ty * 8 + i;
        if (m < M) {
            #pragma unroll
            for (int j = 0; j < 8; j++) {
                int n = n0 + tx * 8 + j;
                Cb[(long)m * c_ld + n] = acc[i][j];
            }
        }
    }
}

// ---------------- fixed-order 8-way partial reduce ----------------------------
__global__ __launch_bounds__(256)
void red8_k(float* __restrict__ dst, const float* __restrict__ src, long stride, long n)
{
    long i = (long)blockIdx.x * 256 + threadIdx.x;
    if (i < n) {
        float a = (src[i] + src[i + stride]) + (src[i + 2 * stride] + src[i + 3 * stride]);
        float b = (src[i + 4 * stride] + src[i + 5 * stride]) + (src[i + 6 * stride] + src[i + 7 * stride]);
        dst[i] = a + b;
    }
}

// ---------------- warp-per-output prep kernels --------------------------------
__global__ __launch_bounds__(256)
void prep1_k(const float* __restrict__ ans,
             const float* __restrict__ Wp, const float* __restrict__ bp,
             const float* __restrict__ Wt, const float* __restrict__ bt)
{
    int b = blockIdx.y;
    int w = threadIdx.x >> 5, lane = threadIdx.x & 31;
    int d = blockIdx.x * 8 + w;
    __shared__ float sA[DD];
    for (int i = threadIdx.x; i < DD; i += 256)
        sA[i] = ans[(long)(b * NLYR + (NLYR - 1)) * DD + i];
    __syncthreads();
    const float* wpr = Wp + (long)d * 3 * DD;
    const float* wtr = Wt + (long)d * 3 * DD;
    float sp = 0.f, st = 0.f;
    #pragma unroll 4
    for (int k = lane; k < DD; k += 32) {
        float a = sA[k];
        sp += wpr[k] * a;
        st += wtr[k] * a;
    }
    #pragma unroll
    for (int o = 16; o > 0; o >>= 1) {
        sp += __shfl_down_sync(0xffffffffu, sp, o);
        st += __shfl_down_sync(0xffffffffu, st, o);
    }
    if (lane == 0) {
        g_cp[b * DD + d] = sp + bp[d];
        g_bias[b * 2 * DD + d] = st + bt[d];   // c_t half
    }
}

__global__ __launch_bounds__(256)
void prep_u_k(const float* __restrict__ Wf1, const float* __restrict__ bf1)
{
    int b = blockIdx.y;
    int w = threadIdx.x >> 5, lane = threadIdx.x & 31;
    int d = blockIdx.x * 8 + w;
    __shared__ float scp[DD];
    for (int i = threadIdx.x; i < DD; i += 256)
        scp[i] = g_cp[b * DD + i];
    __syncthreads();
    const float* wr = Wf1 + (long)d * 2 * DD;
    float s = 0.f;
    #pragma unroll 4
    for (int k = lane; k < DD; k += 32)
        s += wr[k] * scp[k];
    #pragma unroll
    for (int o = 16; o > 0; o >>= 1)
        s += __shfl_down_sync(0xffffffffu, s, o);
    if (lane == 0)
        g_bias[b * 2 * DD + DD + d] = s + bf1[d];   // u half
}

// ---------------- fp16 pack helper ------------------------------------------
__device__ __forceinline__ uint4 pack8h(const float* v) {
    unsigned short h[8];
    #pragma unroll
    for (int i = 0; i < 8; i++) h[i] = __half_as_ushort(__float2half_rn(v[i]));
    uint4 r;
    r.x = h[0] | ((uint32_t)h[1] << 16); r.y = h[2] | ((uint32_t)h[3] << 16);
    r.z = h[4] | ((uint32_t)h[5] << 16); r.w = h[6] | ((uint32_t)h[7] << 16);
    return r;
}

// ---------------- fused prepack: Q image then W image ------------------------
#define QWORK ((long)BQ * MT * 128 * 96)
#define WWORK ((long)BQ * NT * 256 * 96)

__global__ __launch_bounds__(256) void split_k(const float* __restrict__ qps,
                                               const float* __restrict__ ans,
                                               const float* __restrict__ Wt)
{
    long gidx = (long)blockIdx.x * 256 + threadIdx.x;
    if (gidx < QWORK) {
        long idx = gidx;
        int c8 = (int)(idx % 96);
        long t  = idx / 96;
        int r  = (int)(t % 128);
        t /= 128;
        int mt = (int)(t % MT);
        int b  = (int)(t / MT);
        int m = mt * 128 + r;
        int k0 = c8 * 8;
        float v[8];
        if (m < NTOT) {
            const float* src = qps + ((long)(b * NLYR + 1) * NTOT + m) * DD + k0;
            float4 a = ((const float4*)src)[0];
            float4 c = ((const float4*)src)[1];
            v[0]=a.x; v[1]=a.y; v[2]=a.z; v[3]=a.w; v[4]=c.x; v[5]=c.y; v[6]=c.z; v[7]=c.w;
        } else {
            #pragma unroll
            for (int i = 0; i < 8; i++) v[i] = 0.f;
        }
        uint4 hi = pack8h(v);
        int slab = k0 >> 6, kin = k0 & 63;
        uint32_t off = swz128((uint32_t)(r * 128 + kin * 2));
        long base = ((long)(b * MT + mt) * NS64 + slab) * AT64 + off;
        *(uint4*)(g_Qh + base) = hi;
    } else {
        long idx = gidx - QWORK;
        if (idx >= WWORK) return;
        int c8 = (int)(idx % 96);
        long t  = idx / 96;
        int r  = (int)(t % 256);
        t /= 256;
        int nt = (int)(t % NT);
        int b  = (int)(t / NT);
        int j = nt * 256 + r;
        int k0 = c8 * 8;
        const float* Av = ans + (long)(b * NLYR + 1) * DD + k0;
        float a[8], w1[8], w2[8];
        {
            float4 x = ((const float4*)Av)[0], y = ((const float4*)Av)[1];
            a[0]=x.x; a[1]=x.y; a[2]=x.z; a[3]=x.w; a[4]=y.x; a[5]=y.y; a[6]=y.z; a[7]=y.w;
        }
        if (j < DD) {
            const float* wr = Wt + (long)j * 3 * DD;
            float4 x = *(const float4*)(wr + DD + k0),     y = *(const float4*)(wr + DD + k0 + 4);
            float4 u = *(const float4*)(wr + 2 * DD + k0), w = *(const float4*)(wr + 2 * DD + k0 + 4);
            w1[0]=x.x; w1[1]=x.y; w1[2]=x.z; w1[3]=x.w; w1[4]=y.x; w1[5]=y.y; w1[6]=y.z; w1[7]=y.w;
            w2[0]=u.x; w2[1]=u.y; w2[2]=u.z; w2[3]=u.w; w2[4]=w.x; w2[5]=w.y; w2[6]=w.z; w2[7]=w.w;
        } else {
            int d = j - DD;
            const float* gr = g_G + (long)d * 2 * DD;
            float4 x = *(const float4*)(gr + k0),      y = *(const float4*)(gr + k0 + 4);
            float4 u = *(const float4*)(gr + DD + k0), w = *(const float4*)(gr + DD + k0 + 4);
            w1[0]=x.x; w1[1]=x.y; w1[2]=x.z; w1[3]=x.w; w1[4]=y.x; w1[5]=y.y; w1[6]=y.z; w1[7]=y.w;
            w2[0]=u.x; w2[1]=u.y; w2[2]=u.z; w2[3]=u.w; w2[4]=w.x; w2[5]=w.y; w2[6]=w.z; w2[7]=w.w;
        }
        float v[8];
        #pragma unroll
        for (int i = 0; i < 8; i++) v[i] = w1[i] + w2[i] * a[i];
        uint4 hi = pack8h(v);
        int slab = k0 >> 6, kin = k0 & 63;
        uint32_t off = swz128((uint32_t)(r * 128 + kin * 2));
        long base = ((long)(b * NT + nt) * NS64 + slab) * BT64 + off;
        *(uint4*)(g_Wh + base) = hi;
    }
}

// ---------------- HMMA main GEMM (fp16, bulk-copy, empty-mbar pipeline) ------
// stage layout: [A 16K][B 32K] = 48KB; 4-stage ring; NO bias (moved downstream)
__global__ __launch_bounds__(512, 1)
void tgemm_k(float* __restrict__ Y)
{
    extern __shared__ __align__(1024) unsigned char dsm[];
    __shared__ __align__(8) uint64_t s_full[4];
    __shared__ __align__(8) uint64_t s_emb[4];
    uint32_t dbase = smem_u32(dsm);
    uint32_t fb0   = smem_u32(&s_full[0]);
    uint32_t eb0   = smem_u32(&s_emb[0]);

    int tid  = threadIdx.x;
    int lane = tid & 31;
    int w    = tid >> 5;      // 0..15
    int mw   = w & 1;         // 0..1 : 64-row block
    int nw   = w >> 1;        // 0..7 : 32-col block
    int b    = blockIdx.z;
    int nt   = blockIdx.x;    // 0..5
    int mt   = blockIdx.y;    // 0..46

    const unsigned char* qh = g_Qh + ((long)(b * MT + mt) * NS64) * AT64;
    const unsigned char* wh = g_Wh + ((long)(b * NT + nt) * NS64) * BT64;

    float acc[4][4][4];
    #pragma unroll
    for (int i = 0; i < 4; i++)
        #pragma unroll
        for (int j = 0; j < 4; j++)
            #pragma unroll
            for (int k = 0; k < 4; k++) acc[i][j][k] = 0.f;

    if (tid == 0) {
        #pragma unroll
        for (int s = 0; s < 4; s++) {
            mbar_init(fb0 + s * 8, 1);
            mbar_init(eb0 + s * 8, 512);
        }
    }
    asm volatile("fence.proxy.async.shared::cta;" ::: "memory");
    __syncthreads();

    // prologue: stages 0,1,2
    if (tid == 0) {
        #pragma unroll
        for (int s = 0; s < 3; s++) {
            uint32_t mb = fb0 + s * 8;
            uint32_t sb = dbase + (uint32_t)s * STG64;
            mbar_expect(mb, STG64);
            bulkcp(sb,        qh + (long)s * AT64, AT64, mb);
            bulkcp(sb + AT64, wh + (long)s * BT64, BT64, mb);
        }
    }

    for (int i = 0; i < NS64; i++) {
        int s = i & 3;
        mbar_wait(fb0 + s * 8, (i >> 2) & 1);
        // producer: prefetch slab i+3 into stage (i+3)&3 once consumers drained it
        if (tid == 0 && i + 3 < NS64) {
            int sl = i + 3, ss = sl & 3;
            if (sl >= 4) mbar_wait(eb0 + ss * 8, ((sl - 4) >> 2) & 1);
            uint32_t mb = fb0 + ss * 8;
            uint32_t sbw = dbase + (uint32_t)ss * STG64;
            mbar_expect(mb, STG64);
            bulkcp(sbw,        qh + (long)sl * AT64, AT64, mb);
            bulkcp(sbw + AT64, wh + (long)sl * BT64, BT64, mb);
        }

        uint32_t sb  = dbase + (uint32_t)s * STG64;
        uint32_t a_t = sb, b_t = sb + 16384;

        #pragma unroll
        for (int kk = 0; kk < 64; kk += 16) {
            uint32_t Bh[8];
            #pragma unroll
            for (int g = 0; g < 2; g++)
                ldm_x4(&Bh[g * 4], ldm_addr128(b_t, nw * 32 + g * 16, kk, lane));
            #pragma unroll
            for (int mf = 0; mf < 4; mf++) {
                uint32_t Ah[4];
                ldm_x4(Ah, ldm_addr128(a_t, mw * 64 + mf * 16, kk, lane));
                #pragma unroll
                for (int nf = 0; nf < 4; nf++) {
                    int g = nf >> 1, q = nf & 1;
                    mma16816(acc[mf][nf], Ah, Bh[g * 4 + q], Bh[g * 4 + 2 + q]);
                }
            }
        }
        mbar_arrive(eb0 + s * 8);   // this thread done with stage s
    }

    // ---- epilogue: direct STG (raw, bias added downstream) ----
    long yb = (long)b * NTOT * (2 * DD);
    #pragma unroll
    for (int nf = 0; nf < 4; nf++) {
        int col = nt * 256 + nw * 32 + nf * 8 + (lane & 3) * 2;
        #pragma unroll
        for (int mf = 0; mf < 4; mf++) {
            int r0 = mt * 128 + mw * 64 + mf * 16 + (lane >> 2);
            int r1 = r0 + 8;
            float* acp = acc[mf][nf];
            if (r0 < NTOT)
                *(float2*)(Y + yb + (long)r0 * (2 * DD) + col) = make_float2(acp[0], acp[1]);
            if (r1 < NTOT)
                *(float2*)(Y + yb + (long)r1 * (2 * DD) + col) = make_float2(acp[2], acp[3]);
        }
    }
}

// ---------------- group max over passages by table id (adds c_t) -------------
__global__ void tmax_k(const int* __restrict__ tids)
{
    int b   = blockIdx.x / NTOK;
    int tok = blockIdx.x % NTOK;
    int d   = threadIdx.x;
    __shared__ int ids[NP];
    if (threadIdx.x < NP) ids[threadIdx.x] = tids[b * NP + threadIdx.x];
    float ct = g_bias[b * 2 * DD + d];
    float m[NTAB];
    #pragma unroll
    for (int t = 0; t < NTAB; t++) m[t] = -3.0e38f;
    __syncthreads();
    const float* Yb = g_Y + (long)b * NTOT * 2 * DD;
    for (int p = 0; p < NP; p++) {
        float v = Yb[(long)(p * NTOK + tok) * 2 * DD + d];
        int id = ids[p];
        #pragma unroll
        for (int t = 0; t < NTAB; t++)
            if (id == t) m[t] = fmaxf(m[t], v);
    }
    #pragma unroll
    for (int t = 0; t < NTAB; t++)
        g_tmax[(((long)b * NTAB + t) * NTOK + tok) * DD + d] = m[t] + ct;
}

// ---------------- final (adds u) ----------------------------------------------
__global__ void final_k(const float* __restrict__ masks, const int* __restrict__ tids,
                        const float* __restrict__ Wf2, const float* __restrict__ bf2,
                        float* __restrict__ out)
{
    int b = blockIdx.x / NP, p = blockIdx.x % NP;
    int tbl = tids[b * NP + p];
    __shared__ float w2[DD];
    __shared__ float su[DD];
    __shared__ float ms[NTOK];
    __shared__ float red[256];
    for (int i = threadIdx.x; i < DD; i += blockDim.x) {
        w2[i] = Wf2[i];
        su[i] = g_bias[b * 2 * DD + DD + i];
    }
    if (threadIdx.x < NTOK) ms[threadIdx.x] = masks[(b * NP + p) * NTOK + threadIdx.x];
    __syncthreads();

    const float* p1 = g_Y + ((long)b * NTOT + (long)p * NTOK) * 2 * DD + DD;
    const float* p2 = g_p2 + ((long)b * NTAB + tbl) * NTOK * DD;
    float acc = 0.f;
    for (int tok = 0; tok < NTOK; tok++) {
        float m = ms[tok];
        const float* r1 = p1 + (long)tok * 2 * DD;
        const float* r2 = p2 + tok * DD;
        #pragma unroll 3
        for (int d = threadIdx.x; d < DD; d += 256) {
            float v = r1[d] + su[d] + r2[d];
            acc += m * w2[d] * fmaxf(v, 0.f);
        }
    }
    red[threadIdx.x] = acc;
    __syncthreads();
    for (int s = 128; s > 0; s >>= 1) {
        if (threadIdx.x < s) red[threadIdx.x] += red[threadIdx.x + s];
        __syncthreads();
    }
    if (threadIdx.x == 0) {
        float msum = 0.f;
        for (int t = 0; t < NTOK; t++) msum += ms[t];
        out[b * NP + p] = red[0] + bf2[0] * msum;
    }
}

// ---------------- launcher --------------------------------------------------
extern "C" void kernel_launch(void* const* d_in, const int* in_sizes, int n_in,
                              void* d_out, int out_size)
{
    const float* ans   = (const float*)d_in[0];
    const float* qps   = (const float*)d_in[1];
    const float* masks = (const float*)d_in[2];
    const int*   tids  = (const int*)  d_in[3];
    const float* Wp    = (const float*)d_in[4];
    const float* bp    = (const float*)d_in[5];
    const float* Wt    = (const float*)d_in[6];
    const float* bt    = (const float*)d_in[7];
    const float* Wf1   = (const float*)d_in[8];
    const float* bf1   = (const float*)d_in[9];
    const float* Wf2   = (const float*)d_in[10];
    const float* bf2   = (const float*)d_in[11];
    float* out = (float*)d_out;

    void *pG, *pGp, *pY, *pTmax, *pP2, *pP2p;
    cudaGetSymbolAddress(&pG,    g_G);
    cudaGetSymbolAddress(&pGp,   g_Gp);
    cudaGetSymbolAddress(&pY,    g_Y);
    cudaGetSymbolAddress(&pTmax, g_tmax);
    cudaGetSymbolAddress(&pP2,   g_p2);
    cudaGetSymbolAddress(&pP2p,  g_p2p);

    const long GSZ  = (long)DD * 2 * DD;
    const long P2SZ = (long)BQ * NTAB * NTOK * DD;

    // launch 0: G partials, split-K x8
    gemm_k<<<dim3(1536 / 128, 768 / 128, KSPLIT), 256>>>(
        Wf1, 2 * DD, 0,
        Wp + DD, 1, 3 * DD, 0,
        (float*)pGp, 2 * DD, 0, GSZ,
        DD, 2 * DD, DD, KSPLIT);

    // launch 1: reduce G partials
    red8_k<<<(unsigned)((GSZ + 255) / 256), 256>>>((float*)pG, (const float*)pGp, GSZ, GSZ);

    // launch 2: fused Q+W image prepack (needs G)
    {
        long tot = QWORK + WWORK;
        split_k<<<(unsigned)(tot / 256), 256>>>(qps, ans, Wt);
    }

    // launch 3: main tensor GEMM  <-- ncu capture window
    {
        int dyn = 4 * STG64;   // 192KB
        cudaFuncSetAttribute(tgemm_k, cudaFuncAttributeMaxDynamicSharedMemorySize, dyn);
        tgemm_k<<<dim3(NT, MT, BQ), 512, dyn>>>((float*)pY);
    }

    // launch 4,5: prep (c_t, u) — needed by tmax/final only
    prep1_k<<<dim3(96, BQ), 256>>>(ans, Wp, bp, Wt, bt);
    prep_u_k<<<dim3(96, BQ), 256>>>(Wf1, bf1);

    // launch 6: table group-max (+c_t)
    tmax_k<<<BQ * NTOK, DD>>>(tids);

    // launch 7: part2 partials, split-K x8
    gemm_k<<<dim3(768 / 128, (NTAB * NTOK + 127) / 128, BQ * KSPLIT), 256>>>(
        (const float*)pTmax, DD, (long)NTAB * NTOK * DD,
        Wf1 + DD, 2 * DD, 1, 0,
        (float*)pP2p, DD, (long)NTAB * NTOK * DD, P2SZ,
        NTAB * NTOK, DD, DD, KSPLIT);

    // launch 8: reduce part2 partials
    red8_k<<<(unsigned)((P2SZ + 255) / 256), 256>>>((float*)pP2, (const float*)pP2p, P2SZ, P2SZ);

    // launch 9: final masked reduction (+u)
    final_k<<<BQ * NP, 256>>>(masks, tids, Wf2, bf2, out);
}

// round 13
// speedup vs baseline: 1.0896x; 1.0896x over previous
#include <cuda_runtime.h>
#include <cuda_fp16.h>
#include <cstdint>

// Problem constants (fixed by setup_inputs)
#define BQ   4
#define NLYR 2
#define NP   100
#define NTOK 60
#define NTOT 6000
#define DD   768
#define NTAB 10

#define MT   47          // m tiles of 128 (6016 >= 6000)
#define NT   6           // 256-wide W image tiles (1536)
#define NT2  12          // CTA n tiles of 128
#define NS64 12          // k slabs of 64
#define AT64 16384       // 128 rows x 64 k fp16 = 16KB
#define BT64 32768       // 256 rows x 64 k fp16 = 32KB (image slab)
#define HBT  16384       // 128-row half of a B image slab
#define STG2 32768       // stage: A 16K + Bhalf 16K

#define KSPLIT 4

// ---------------- scratch ---------------------------------------------------
__device__ float g_G[DD * 2 * DD];
__device__ float g_Gp[KSPLIT * DD * 2 * DD];
__device__ float g_cp[BQ * DD];
__device__ float g_bias[BQ * 2 * DD];
__device__ float g_Y[(size_t)BQ * NTOT * 2 * DD];
__device__ float g_tmax[BQ * NTAB * NTOK * DD];
__device__ float g_p2[BQ * NTAB * NTOK * DD];
__device__ float g_p2p[KSPLIT * BQ * NTAB * NTOK * DD];
// pre-swizzled fp16 tile images (SW128, 128B rows, 64-k slabs)
__device__ unsigned char g_Qh[(size_t)BQ * MT * NS64 * AT64];
__device__ unsigned char g_Wh[(size_t)BQ * NT * NS64 * BT64];

// ---------------- PTX helpers ----------------------------------------------
__device__ __forceinline__ uint32_t smem_u32(const void* p) {
    uint32_t a;
    asm("{ .reg .u64 t; cvta.to.shared.u64 t, %1; cvt.u32.u64 %0, t; }" : "=r"(a) : "l"(p));
    return a;
}
__device__ __forceinline__ void ldm_x4(uint32_t* r, uint32_t addr) {
    asm volatile("ldmatrix.sync.aligned.m8n8.x4.shared.b16 {%0,%1,%2,%3}, [%4];"
                 : "=r"(r[0]), "=r"(r[1]), "=r"(r[2]), "=r"(r[3]) : "r"(addr));
}
__device__ __forceinline__ void mma16816(float* d, const uint32_t* a,
                                         uint32_t b0, uint32_t b1) {
    asm volatile(
        "mma.sync.aligned.m16n8k16.row.col.f32.f16.f16.f32 "
        "{%0,%1,%2,%3}, {%4,%5,%6,%7}, {%8,%9}, {%0,%1,%2,%3};"
        : "+f"(d[0]), "+f"(d[1]), "+f"(d[2]), "+f"(d[3])
        : "r"(a[0]), "r"(a[1]), "r"(a[2]), "r"(a[3]), "r"(b0), "r"(b1));
}
__device__ __forceinline__ uint32_t ldm_addr128(uint32_t tilebase, int row0, int k0, int lane) {
    int row = row0 + (lane & 15);
    int kc  = k0 + ((lane >> 4) << 3);
    uint32_t off = (uint32_t)(row * 128 + kc * 2);
    off ^= (off >> 3) & 0x70;
    return tilebase + off;
}
__device__ __forceinline__ uint32_t swz128(uint32_t off) {
    return off ^ ((off >> 3) & 0x70);
}
// ---- bulk-copy + mbarrier ----
__device__ __forceinline__ void mbar_init(uint32_t mb, uint32_t cnt) {
    asm volatile("mbarrier.init.shared.b64 [%0], %1;" :: "r"(mb), "r"(cnt) : "memory");
}
__device__ __forceinline__ void mbar_expect(uint32_t mb, uint32_t bytes) {
    asm volatile("mbarrier.arrive.expect_tx.shared.b64 _, [%0], %1;"
                 :: "r"(mb), "r"(bytes) : "memory");
}
__device__ __forceinline__ void mbar_arrive(uint32_t mb) {
    asm volatile("mbarrier.arrive.shared.b64 _, [%0];" :: "r"(mb) : "memory");
}
__device__ __forceinline__ void bulkcp(uint32_t dst, const void* src, uint32_t bytes, uint32_t mb) {
    asm volatile("cp.async.bulk.shared::cluster.global.mbarrier::complete_tx::bytes "
                 "[%0], [%1], %2, [%3];"
                 :: "r"(dst), "l"(src), "r"(bytes), "r"(mb) : "memory");
}
__device__ __forceinline__ void mbar_wait(uint32_t mb, uint32_t parity) {
    asm volatile(
        "{\n\t.reg .pred P1;\n\t"
        "WAITLP_%=:\n\t"
        "mbarrier.try_wait.parity.acquire.cta.shared::cta.b64 P1, [%0], %1, 0x989680;\n\t"
        "@P1 bra.uni WAITDN_%=;\n\t"
        "bra.uni WAITLP_%=;\n\t"
        "WAITDN_%=:\n\t}"
        :: "r"(mb), "r"(parity) : "memory");
}

// ---------------- SIMT GEMM with split-K (small ops) -------------------------
__global__ __launch_bounds__(256)
void gemm_k(const float* __restrict__ A, long a_rs, long a_bs,
            const float* __restrict__ Bm, long b_ns, long b_ks, long b_bs,
            float* __restrict__ C, long c_ld, long c_bs, long c_ss,
            int M, int N, int K, int nsplit)
{
    const int BM = 128, BN = 128, BK = 16;
    __shared__ float As[BK][BM + 4];
    __shared__ float Bs[BK][BN + 4];
    int bz = blockIdx.z / nsplit;
    int sp = blockIdx.z % nsplit;
    int klen = K / nsplit;
    int kbeg = sp * klen;
    const float* Ab = A  + (long)bz * a_bs;
    const float* Bb = Bm + (long)bz * b_bs;
    float*       Cb = C  + (long)bz * c_bs + (long)sp * c_ss;
    int m0 = blockIdx.y * BM, n0 = blockIdx.x * BN;
    int tid = threadIdx.x, tx = tid & 15, ty = tid >> 4;
    float acc[8][8];
    #pragma unroll
    for (int i = 0; i < 8; i++)
        #pragma unroll
        for (int j = 0; j < 8; j++) acc[i][j] = 0.f;
    for (int k0 = kbeg; k0 < kbeg + klen; k0 += BK) {
        #pragma unroll
        for (int i = 0; i < 8; i++) {
            int e = tid + i * 256, m = e >> 4, k = e & 15;
            float v = 0.f;
            if (m0 + m < M) v = Ab[(long)(m0 + m) * a_rs + (k0 + k)];
            As[k][m] = v;
        }
        if (b_ks == 1) {
            #pragma unroll
            for (int i = 0; i < 8; i++) {
                int e = tid + i * 256, n = e >> 4, k = e & 15;
                Bs[k][n] = Bb[(long)(n0 + n) * b_ns + (long)(k0 + k) * b_ks];
            }
        } else {
            #pragma unroll
            for (int i = 0; i < 8; i++) {
                int e = tid + i * 256, k = e >> 7, n = e & 127;
                Bs[k][n] = Bb[(long)(n0 + n) * b_ns + (long)(k0 + k) * b_ks];
            }
        }
        __syncthreads();
        #pragma unroll
        for (int kk = 0; kk < BK; kk++) {
            float a[8], bb[8];
            #pragma unroll
            for (int i = 0; i < 8; i++) a[i]  = As[kk][ty * 8 + i];
            #pragma unroll
            for (int j = 0; j < 8; j++) bb[j] = Bs[kk][tx * 8 + j];
            #pragma unroll
            for (int i = 0; i < 8; i++)
                #pragma unroll
                for (int j = 0; j < 8; j++) acc[i][j] += a[i] * bb[j];
        }
        __syncthreads();
    }
    #pragma unroll
    for (int i = 0; i < 8; i++) {
        int m = m0 + ty * 8 + i;
        if (m < M) {
            #pragma unroll
            for (int j = 0; j < 8; j++) {
                int n = n0 + tx * 8 + j;
                Cb[(long)m * c_ld + n] = acc[i][j];
            }
        }
    }
}

// ---------------- fixed-order 4-way partial reduce ----------------------------
__global__ __launch_bounds__(256)
void red4_k(float* __restrict__ dst, const float* __restrict__ src, long stride, long n)
{
    long i = (long)blockIdx.x * 256 + threadIdx.x;
    if (i < n)
        dst[i] = (src[i] + src[i + stride]) + (src[i + 2 * stride] + src[i + 3 * stride]);
}

// ---------------- warp-per-output prep kernels --------------------------------
__global__ __launch_bounds__(256)
void prep1_k(const float* __restrict__ ans,
             const float* __restrict__ Wp, const float* __restrict__ bp,
             const float* __restrict__ Wt, const float* __restrict__ bt)
{
    int b = blockIdx.y;
    int w = threadIdx.x >> 5, lane = threadIdx.x & 31;
    int d = blockIdx.x * 8 + w;
    __shared__ float sA[DD];
    for (int i = threadIdx.x; i < DD; i += 256)
        sA[i] = ans[(long)(b * NLYR + (NLYR - 1)) * DD + i];
    __syncthreads();
    const float* wpr = Wp + (long)d * 3 * DD;
    const float* wtr = Wt + (long)d * 3 * DD;
    float sp = 0.f, st = 0.f;
    #pragma unroll 4
    for (int k = lane; k < DD; k += 32) {
        float a = sA[k];
        sp += wpr[k] * a;
        st += wtr[k] * a;
    }
    #pragma unroll
    for (int o = 16; o > 0; o >>= 1) {
        sp += __shfl_down_sync(0xffffffffu, sp, o);
        st += __shfl_down_sync(0xffffffffu, st, o);
    }
    if (lane == 0) {
        g_cp[b * DD + d] = sp + bp[d];
        g_bias[b * 2 * DD + d] = st + bt[d];   // c_t half
    }
}

__global__ __launch_bounds__(256)
void prep_u_k(const float* __restrict__ Wf1, const float* __restrict__ bf1)
{
    int b = blockIdx.y;
    int w = threadIdx.x >> 5, lane = threadIdx.x & 31;
    int d = blockIdx.x * 8 + w;
    __shared__ float scp[DD];
    for (int i = threadIdx.x; i < DD; i += 256)
        scp[i] = g_cp[b * DD + i];
    __syncthreads();
    const float* wr = Wf1 + (long)d * 2 * DD;
    float s = 0.f;
    #pragma unroll 4
    for (int k = lane; k < DD; k += 32)
        s += wr[k] * scp[k];
    #pragma unroll
    for (int o = 16; o > 0; o >>= 1)
        s += __shfl_down_sync(0xffffffffu, s, o);
    if (lane == 0)
        g_bias[b * 2 * DD + DD + d] = s + bf1[d];   // u half
}

// ---------------- fp16 pack helper ------------------------------------------
__device__ __forceinline__ uint4 pack8h(const float* v) {
    unsigned short h[8];
    #pragma unroll
    for (int i = 0; i < 8; i++) h[i] = __half_as_ushort(__float2half_rn(v[i]));
    uint4 r;
    r.x = h[0] | ((uint32_t)h[1] << 16); r.y = h[2] | ((uint32_t)h[3] << 16);
    r.z = h[4] | ((uint32_t)h[5] << 16); r.w = h[6] | ((uint32_t)h[7] << 16);
    return r;
}

// Q -> SW128 fp16 tile image. thread = (b, mt, r, c8)
__global__ __launch_bounds__(256) void qsplit_k(const float* __restrict__ qps)
{
    long idx = (long)blockIdx.x * 256 + threadIdx.x;
    int c8 = (int)(idx % 96);
    long t  = idx / 96;
    int r  = (int)(t % 128);
    t /= 128;
    int mt = (int)(t % MT);
    int b  = (int)(t / MT);
    if (b >= BQ) return;
    int m = mt * 128 + r;
    int k0 = c8 * 8;
    float v[8];
    if (m < NTOT) {
        const float* src = qps + ((long)(b * NLYR + 1) * NTOT + m) * DD + k0;
        float4 a = ((const float4*)src)[0];
        float4 c = ((const float4*)src)[1];
        v[0]=a.x; v[1]=a.y; v[2]=a.z; v[3]=a.w; v[4]=c.x; v[5]=c.y; v[6]=c.z; v[7]=c.w;
    } else {
        #pragma unroll
        for (int i = 0; i < 8; i++) v[i] = 0.f;
    }
    uint4 hi = pack8h(v);
    int slab = k0 >> 6, kin = k0 & 63;
    uint32_t off = swz128((uint32_t)(r * 128 + kin * 2));
    long base = ((long)(b * MT + mt) * NS64 + slab) * AT64 + off;
    *(uint4*)(g_Qh + base) = hi;
}

// Wbig -> SW128 fp16 tile image. thread = (b, nt, r, c8)
__global__ __launch_bounds__(256) void wsplit_k(const float* __restrict__ ans,
                                                const float* __restrict__ Wt)
{
    long idx = (long)blockIdx.x * 256 + threadIdx.x;
    int c8 = (int)(idx % 96);
    long t  = idx / 96;
    int r  = (int)(t % 256);
    t /= 256;
    int nt = (int)(t % NT);
    int b  = (int)(t / NT);
    if (b >= BQ) return;
    int j = nt * 256 + r;
    int k0 = c8 * 8;
    const float* Av = ans + (long)(b * NLYR + 1) * DD + k0;
    float a[8], w1[8], w2[8];
    {
        float4 x = ((const float4*)Av)[0], y = ((const float4*)Av)[1];
        a[0]=x.x; a[1]=x.y; a[2]=x.z; a[3]=x.w; a[4]=y.x; a[5]=y.y; a[6]=y.z; a[7]=y.w;
    }
    if (j < DD) {
        const float* wr = Wt + (long)j * 3 * DD;
        float4 x = *(const float4*)(wr + DD + k0),     y = *(const float4*)(wr + DD + k0 + 4);
        float4 u = *(const float4*)(wr + 2 * DD + k0), w = *(const float4*)(wr + 2 * DD + k0 + 4);
        w1[0]=x.x; w1[1]=x.y; w1[2]=x.z; w1[3]=x.w; w1[4]=y.x; w1[5]=y.y; w1[6]=y.z; w1[7]=y.w;
        w2[0]=u.x; w2[1]=u.y; w2[2]=u.z; w2[3]=u.w; w2[4]=w.x; w2[5]=w.y; w2[6]=w.z; w2[7]=w.w;
    } else {
        int d = j - DD;
        const float* gr = g_G + (long)d * 2 * DD;
        float4 x = *(const float4*)(gr + k0),      y = *(const float4*)(gr + k0 + 4);
        float4 u = *(const float4*)(gr + DD + k0), w = *(const float4*)(gr + DD + k0 + 4);
        w1[0]=x.x; w1[1]=x.y; w1[2]=x.z; w1[3]=x.w; w1[4]=y.x; w1[5]=y.y; w1[6]=y.z; w1[7]=y.w;
        w2[0]=u.x; w2[1]=u.y; w2[2]=u.z; w2[3]=u.w; w2[4]=w.x; w2[5]=w.y; w2[6]=w.z; w2[7]=w.w;
    }
    float v[8];
    #pragma unroll
    for (int i = 0; i < 8; i++) v[i] = w1[i] + w2[i] * a[i];
    uint4 hi = pack8h(v);
    int slab = k0 >> 6, kin = k0 & 63;
    uint32_t off = swz128((uint32_t)(r * 128 + kin * 2));
    long base = ((long)(b * NT + nt) * NS64 + slab) * BT64 + off;
    *(uint4*)(g_Wh + base) = hi;
}

// ---------------- HMMA main GEMM: 128x128 CTA tile, 2 CTAs/SM ----------------
// stage layout: [A 16K][Bhalf 16K] = 32KB; 2-stage ring; bias fused.
__global__ __launch_bounds__(256, 2)
void tgemm_k(const float* __restrict__ bias, float* __restrict__ Y)
{
    extern __shared__ __align__(1024) unsigned char dsm[];
    __shared__ __align__(8) uint64_t s_full[2];
    __shared__ __align__(8) uint64_t s_emb[2];
    uint32_t dbase = smem_u32(dsm);
    uint32_t fb0   = smem_u32(&s_full[0]);
    uint32_t eb0   = smem_u32(&s_emb[0]);

    int tid  = threadIdx.x;
    int lane = tid & 31;
    int w    = tid >> 5;      // 0..7
    int mw   = w & 1;         // 0..1 : 64-row block
    int nw   = w >> 1;        // 0..3 : 32-col block
    int b    = blockIdx.z;
    int nt2  = blockIdx.x;    // 0..11 : 128-col CTA tiles
    int mt   = blockIdx.y;    // 0..46

    const unsigned char* qh = g_Qh + ((long)(b * MT + mt) * NS64) * AT64;
    const unsigned char* wh = g_Wh + ((long)(b * NT + (nt2 >> 1)) * NS64) * BT64
                                   + (long)(nt2 & 1) * HBT;

    float acc[4][4][4];
    #pragma unroll
    for (int i = 0; i < 4; i++)
        #pragma unroll
        for (int j = 0; j < 4; j++)
            #pragma unroll
            for (int k = 0; k < 4; k++) acc[i][j][k] = 0.f;

    if (tid == 0) {
        #pragma unroll
        for (int s = 0; s < 2; s++) {
            mbar_init(fb0 + s * 8, 1);
            mbar_init(eb0 + s * 8, 256);
        }
    }
    asm volatile("fence.proxy.async.shared::cta;" ::: "memory");
    __syncthreads();

    // prologue: stages 0,1  (B slab stride within image is BT64)
    if (tid == 0) {
        #pragma unroll
        for (int s = 0; s < 2; s++) {
            uint32_t mb = fb0 + s * 8;
            uint32_t sb = dbase + (uint32_t)s * STG2;
            mbar_expect(mb, STG2);
            bulkcp(sb,         qh + (long)s * AT64, AT64, mb);
            bulkcp(sb + AT64,  wh + (long)s * BT64, HBT,  mb);
        }
    }

    for (int i = 0; i < NS64; i++) {
        int s = i & 1;
        mbar_wait(fb0 + s * 8, (i >> 1) & 1);

        uint32_t sb  = dbase + (uint32_t)s * STG2;
        uint32_t a_t = sb, b_t = sb + AT64;

        #pragma unroll
        for (int kk = 0; kk < 64; kk += 16) {
            uint32_t Bh[8];
            #pragma unroll
            for (int g = 0; g < 2; g++)
                ldm_x4(&Bh[g * 4], ldm_addr128(b_t, nw * 32 + g * 16, kk, lane));
            #pragma unroll
            for (int mf = 0; mf < 4; mf++) {
                uint32_t Ah[4];
                ldm_x4(Ah, ldm_addr128(a_t, mw * 64 + mf * 16, kk, lane));
                #pragma unroll
                for (int nf = 0; nf < 4; nf++) {
                    int g = nf >> 1, q = nf & 1;
                    mma16816(acc[mf][nf], Ah, Bh[g * 4 + q], Bh[g * 4 + 2 + q]);
                }
            }
        }
        mbar_arrive(eb0 + s * 8);   // done with stage s for slab i

        // producer: refill stage s with slab i+2 once all 256 drained slab i
        if (tid == 0 && i + 2 < NS64) {
            mbar_wait(eb0 + s * 8, (i >> 1) & 1);
            int sl = i + 2;
            uint32_t mb = fb0 + s * 8;
            mbar_expect(mb, STG2);
            bulkcp(sb,        qh + (long)sl * AT64, AT64, mb);
            bulkcp(sb + AT64, wh + (long)sl * BT64, HBT,  mb);
        }
    }

    // ---- epilogue: direct STG with fused bias ----
    long yb = (long)b * NTOT * (2 * DD);
    #pragma unroll
    for (int nf = 0; nf < 4; nf++) {
        int col = nt2 * 128 + nw * 32 + nf * 8 + (lane & 3) * 2;
        float bv0 = bias[b * 2 * DD + col];
        float bv1 = bias[b * 2 * DD + col + 1];
        #pragma unroll
        for (int mf = 0; mf < 4; mf++) {
            int r0 = mt * 128 + mw * 64 + mf * 16 + (lane >> 2);
            int r1 = r0 + 8;
            float* acp = acc[mf][nf];
            if (r0 < NTOT)
                *(float2*)(Y + yb + (long)r0 * (2 * DD) + col) = make_float2(acp[0] + bv0, acp[1] + bv1);
            if (r1 < NTOT)
                *(float2*)(Y + yb + (long)r1 * (2 * DD) + col) = make_float2(acp[2] + bv0, acp[3] + bv1);
        }
    }
}

// ---------------- group max over passages by table id -----------------------
__global__ void tmax_k(const int* __restrict__ tids)
{
    int b   = blockIdx.x / NTOK;
    int tok = blockIdx.x % NTOK;
    int d   = threadIdx.x;
    __shared__ int ids[NP];
    if (threadIdx.x < NP) ids[threadIdx.x] = tids[b * NP + threadIdx.x];
    float m[NTAB];
    #pragma unroll
    for (int t = 0; t < NTAB; t++) m[t] = -3.0e38f;
    __syncthreads();
    const float* Yb = g_Y + (long)b * NTOT * 2 * DD;
    for (int p = 0; p < NP; p++) {
        float v = Yb[(long)(p * NTOK + tok) * 2 * DD + d];
        int id = ids[p];
        #pragma unroll
        for (int t = 0; t < NTAB; t++)
            if (id == t) m[t] = fmaxf(m[t], v);
    }
    #pragma unroll
    for (int t = 0; t < NTAB; t++)
        g_tmax[(((long)b * NTAB + t) * NTOK + tok) * DD + d] = m[t];
}

// ---------------- final -----------------------------------------------------
__global__ void final_k(const float* __restrict__ masks, const int* __restrict__ tids,
                        const float* __restrict__ Wf2, const float* __restrict__ bf2,
                        float* __restrict__ out)
{
    int b = blockIdx.x / NP, p = blockIdx.x % NP;
    int tbl = tids[b * NP + p];
    __shared__ float w2[DD];
    __shared__ float ms[NTOK];
    __shared__ float red[256];
    for (int i = threadIdx.x; i < DD; i += blockDim.x) w2[i] = Wf2[i];
    if (threadIdx.x < NTOK) ms[threadIdx.x] = masks[(b * NP + p) * NTOK + threadIdx.x];
    __syncthreads();

    const float* p1 = g_Y + ((long)b * NTOT + (long)p * NTOK) * 2 * DD + DD;
    const float* p2 = g_p2 + ((long)b * NTAB + tbl) * NTOK * DD;
    float acc = 0.f;
    for (int tok = 0; tok < NTOK; tok++) {
        float m = ms[tok];
        const float* r1 = p1 + (long)tok * 2 * DD;
        const float* r2 = p2 + tok * DD;
        #pragma unroll 3
        for (int d = threadIdx.x; d < DD; d += 256) {
            float v = r1[d] + r2[d];
            acc += m * w2[d] * fmaxf(v, 0.f);
        }
    }
    red[threadIdx.x] = acc;
    __syncthreads();
    for (int s = 128; s > 0; s >>= 1) {
        if (threadIdx.x < s) red[threadIdx.x] += red[threadIdx.x + s];
        __syncthreads();
    }
    if (threadIdx.x == 0) {
        float msum = 0.f;
        for (int t = 0; t < NTOK; t++) msum += ms[t];
        out[b * NP + p] = red[0] + bf2[0] * msum;
    }
}

// ---------------- launcher --------------------------------------------------
extern "C" void kernel_launch(void* const* d_in, const int* in_sizes, int n_in,
                              void* d_out, int out_size)
{
    const float* ans   = (const float*)d_in[0];
    const float* qps   = (const float*)d_in[1];
    const float* masks = (const float*)d_in[2];
    const int*   tids  = (const int*)  d_in[3];
    const float* Wp    = (const float*)d_in[4];
    const float* bp    = (const float*)d_in[5];
    const float* Wt    = (const float*)d_in[6];
    const float* bt    = (const float*)d_in[7];
    const float* Wf1   = (const float*)d_in[8];
    const float* bf1   = (const float*)d_in[9];
    const float* Wf2   = (const float*)d_in[10];
    const float* bf2   = (const float*)d_in[11];
    float* out = (float*)d_out;

    void *pG, *pGp, *pBias, *pY, *pTmax, *pP2, *pP2p;
    cudaGetSymbolAddress(&pG,    g_G);
    cudaGetSymbolAddress(&pGp,   g_Gp);
    cudaGetSymbolAddress(&pBias, g_bias);
    cudaGetSymbolAddress(&pY,    g_Y);
    cudaGetSymbolAddress(&pTmax, g_tmax);
    cudaGetSymbolAddress(&pP2,   g_p2);
    cudaGetSymbolAddress(&pP2p,  g_p2p);

    const long GSZ  = (long)DD * 2 * DD;
    const long P2SZ = (long)BQ * NTAB * NTOK * DD;

    // launch 0: warp-reduce c_p, c_t
    prep1_k<<<dim3(96, BQ), 256>>>(ans, Wp, bp, Wt, bt);
    // launch 1: warp-reduce u
    prep_u_k<<<dim3(96, BQ), 256>>>(Wf1, bf1);

    // launch 2: Q image prepack
    {
        long tq = (long)BQ * MT * 128 * 96;
        qsplit_k<<<(unsigned)((tq + 255) / 256), 256>>>(qps);
    }

    // launch 3: G partials, split-K x4
    gemm_k<<<dim3(1536 / 128, 768 / 128, KSPLIT), 256>>>(
        Wf1, 2 * DD, 0,
        Wp + DD, 1, 3 * DD, 0,
        (float*)pGp, 2 * DD, 0, GSZ,
        DD, 2 * DD, DD, KSPLIT);

    // launch 4: reduce G partials
    red4_k<<<(unsigned)((GSZ + 255) / 256), 256>>>((float*)pG, (const float*)pGp, GSZ, GSZ);

    // launch 5: W image prepack (needs G)
    {
        long tw = (long)BQ * NT * 256 * 96;
        wsplit_k<<<(unsigned)((tw + 255) / 256), 256>>>(ans, Wt);
    }

    // launch 6: main tensor GEMM, 128x128 CTA tiles, 2 CTAs/SM
    {
        int dyn = 2 * STG2;   // 64KB
        cudaFuncSetAttribute(tgemm_k, cudaFuncAttributeMaxDynamicSharedMemorySize, dyn);
        tgemm_k<<<dim3(NT2, MT, BQ), 256, dyn>>>((const float*)pBias, (float*)pY);
    }

    // launch 7: table group-max
    tmax_k<<<BQ * NTOK, DD>>>(tids);

    // launch 8: part2 partials = tmax @ Wf1_a^T, split-K x4
    gemm_k<<<dim3(768 / 128, (NTAB * NTOK + 127) / 128, BQ * KSPLIT), 256>>>(
        (const float*)pTmax, DD, (long)NTAB * NTOK * DD,
        Wf1 + DD, 2 * DD, 1, 0,
        (float*)pP2p, DD, (long)NTAB * NTOK * DD, P2SZ,
        NTAB * NTOK, DD, DD, KSPLIT);

    // launch 9: reduce part2 partials
    red4_k<<<(unsigned)((P2SZ + 255) / 256), 256>>>((float*)pP2, (const float*)pP2p, P2SZ, P2SZ);

    // launch 10: final masked reduction
    final_k<<<BQ * NP, 256>>>(masks, tids, Wf2, bf2, out);
}

// round 14
// speedup vs baseline: 1.6376x; 1.5030x over previous
#include <cuda_runtime.h>
#include <cuda_fp16.h>
#include <cstdint>

// Problem constants (fixed by setup_inputs)
#define BQ   4
#define NLYR 2
#define NP   100
#define NTOK 60
#define NTOT 6000
#define DD   768
#define NTAB 10

#define MT   47          // m tiles of 128 (6016 >= 6000)
#define NT   6           // 256-wide W image tiles (1536)
#define NT2  12          // CTA n tiles of 128
#define NS64 12          // k slabs of 64
#define AT64 16384       // 128 rows x 64 k fp16 = 16KB
#define BT64 32768       // 256 rows x 64 k fp16 = 32KB (image slab)
#define HBT  16384       // 128-row half of a B image slab
#define STG2 32768       // stage: 16K + 16K

// ---------------- scratch ---------------------------------------------------
__device__ float g_G[DD * 2 * DD];
__device__ float g_cp[BQ * DD];
__device__ float g_bias[BQ * 2 * DD];
__device__ float g_Y[(size_t)BQ * NTOT * 2 * DD];
__device__ float g_tmax[BQ * NTAB * NTOK * DD];
__device__ float g_p2[BQ * NTAB * NTOK * DD];
// pre-swizzled fp16 tile images (SW128, 128B rows, 64-k slabs)
__device__ unsigned char g_Qh[(size_t)BQ * MT * NS64 * AT64];
__device__ unsigned char g_Wh[(size_t)BQ * NT * NS64 * BT64];
// fp16 images for the small tensor GEMMs (128-row x 64-k tiles)
__device__ unsigned char g_Wf1pI[6 * NS64 * AT64];           // A: Wf1_p  (768 rows)
__device__ unsigned char g_WpI[12 * NS64 * AT64];            // B: Wp_{Q|AQ} (1536 rows)
__device__ unsigned char g_Wf1aI[6 * NS64 * AT64];           // B: Wf1_a (768 rows)
__device__ unsigned char g_TmI[(size_t)BQ * 5 * NS64 * AT64]; // A: tmax (640 rows/batch)

// ---------------- PTX helpers ----------------------------------------------
__device__ __forceinline__ uint32_t smem_u32(const void* p) {
    uint32_t a;
    asm("{ .reg .u64 t; cvta.to.shared.u64 t, %1; cvt.u32.u64 %0, t; }" : "=r"(a) : "l"(p));
    return a;
}
__device__ __forceinline__ void ldm_x4(uint32_t* r, uint32_t addr) {
    asm volatile("ldmatrix.sync.aligned.m8n8.x4.shared.b16 {%0,%1,%2,%3}, [%4];"
                 : "=r"(r[0]), "=r"(r[1]), "=r"(r[2]), "=r"(r[3]) : "r"(addr));
}
__device__ __forceinline__ void mma16816(float* d, const uint32_t* a,
                                         uint32_t b0, uint32_t b1) {
    asm volatile(
        "mma.sync.aligned.m16n8k16.row.col.f32.f16.f16.f32 "
        "{%0,%1,%2,%3}, {%4,%5,%6,%7}, {%8,%9}, {%0,%1,%2,%3};"
        : "+f"(d[0]), "+f"(d[1]), "+f"(d[2]), "+f"(d[3])
        : "r"(a[0]), "r"(a[1]), "r"(a[2]), "r"(a[3]), "r"(b0), "r"(b1));
}
__device__ __forceinline__ uint32_t ldm_addr128(uint32_t tilebase, int row0, int k0, int lane) {
    int row = row0 + (lane & 15);
    int kc  = k0 + ((lane >> 4) << 3);
    uint32_t off = (uint32_t)(row * 128 + kc * 2);
    off ^= (off >> 3) & 0x70;
    return tilebase + off;
}
__device__ __forceinline__ uint32_t swz128(uint32_t off) {
    return off ^ ((off >> 3) & 0x70);
}
// ---- bulk-copy + mbarrier ----
__device__ __forceinline__ void mbar_init(uint32_t mb, uint32_t cnt) {
    asm volatile("mbarrier.init.shared.b64 [%0], %1;" :: "r"(mb), "r"(cnt) : "memory");
}
__device__ __forceinline__ void mbar_expect(uint32_t mb, uint32_t bytes) {
    asm volatile("mbarrier.arrive.expect_tx.shared.b64 _, [%0], %1;"
                 :: "r"(mb), "r"(bytes) : "memory");
}
__device__ __forceinline__ void mbar_arrive(uint32_t mb) {
    asm volatile("mbarrier.arrive.shared.b64 _, [%0];" :: "r"(mb) : "memory");
}
__device__ __forceinline__ void bulkcp(uint32_t dst, const void* src, uint32_t bytes, uint32_t mb) {
    asm volatile("cp.async.bulk.shared::cluster.global.mbarrier::complete_tx::bytes "
                 "[%0], [%1], %2, [%3];"
                 :: "r"(dst), "l"(src), "r"(bytes), "r"(mb) : "memory");
}
__device__ __forceinline__ void mbar_wait(uint32_t mb, uint32_t parity) {
    asm volatile(
        "{\n\t.reg .pred P1;\n\t"
        "WAITLP_%=:\n\t"
        "mbarrier.try_wait.parity.acquire.cta.shared::cta.b64 P1, [%0], %1, 0x989680;\n\t"
        "@P1 bra.uni WAITDN_%=;\n\t"
        "bra.uni WAITLP_%=;\n\t"
        "WAITDN_%=:\n\t}"
        :: "r"(mb), "r"(parity) : "memory");
}

// ---------------- warp-per-output prep kernels --------------------------------
__global__ __launch_bounds__(256)
void prep1_k(const float* __restrict__ ans,
             const float* __restrict__ Wp, const float* __restrict__ bp,
             const float* __restrict__ Wt, const float* __restrict__ bt)
{
    int b = blockIdx.y;
    int w = threadIdx.x >> 5, lane = threadIdx.x & 31;
    int d = blockIdx.x * 8 + w;
    __shared__ float sA[DD];
    for (int i = threadIdx.x; i < DD; i += 256)
        sA[i] = ans[(long)(b * NLYR + (NLYR - 1)) * DD + i];
    __syncthreads();
    const float* wpr = Wp + (long)d * 3 * DD;
    const float* wtr = Wt + (long)d * 3 * DD;
    float sp = 0.f, st = 0.f;
    #pragma unroll 4
    for (int k = lane; k < DD; k += 32) {
        float a = sA[k];
        sp += wpr[k] * a;
        st += wtr[k] * a;
    }
    #pragma unroll
    for (int o = 16; o > 0; o >>= 1) {
        sp += __shfl_down_sync(0xffffffffu, sp, o);
        st += __shfl_down_sync(0xffffffffu, st, o);
    }
    if (lane == 0) {
        g_cp[b * DD + d] = sp + bp[d];
        g_bias[b * 2 * DD + d] = st + bt[d];   // c_t half
    }
}

__global__ __launch_bounds__(256)
void prep_u_k(const float* __restrict__ Wf1, const float* __restrict__ bf1)
{
    int b = blockIdx.y;
    int w = threadIdx.x >> 5, lane = threadIdx.x & 31;
    int d = blockIdx.x * 8 + w;
    __shared__ float scp[DD];
    for (int i = threadIdx.x; i < DD; i += 256)
        scp[i] = g_cp[b * DD + i];
    __syncthreads();
    const float* wr = Wf1 + (long)d * 2 * DD;
    float s = 0.f;
    #pragma unroll 4
    for (int k = lane; k < DD; k += 32)
        s += wr[k] * scp[k];
    #pragma unroll
    for (int o = 16; o > 0; o >>= 1)
        s += __shfl_down_sync(0xffffffffu, s, o);
    if (lane == 0)
        g_bias[b * 2 * DD + DD + d] = s + bf1[d];   // u half
}

// ---------------- fp16 pack helper ------------------------------------------
__device__ __forceinline__ uint4 pack8h(const float* v) {
    unsigned short h[8];
    #pragma unroll
    for (int i = 0; i < 8; i++) h[i] = __half_as_ushort(__float2half_rn(v[i]));
    uint4 r;
    r.x = h[0] | ((uint32_t)h[1] << 16); r.y = h[2] | ((uint32_t)h[3] << 16);
    r.z = h[4] | ((uint32_t)h[5] << 16); r.w = h[6] | ((uint32_t)h[7] << 16);
    return r;
}
__device__ __forceinline__ void img_store(unsigned char* img, int tile, int r, int k0, uint4 v) {
    int slab = k0 >> 6, kin = k0 & 63;
    uint32_t off = swz128((uint32_t)(r * 128 + kin * 2));
    long base = ((long)tile * NS64 + slab) * AT64 + off;
    *(uint4*)(img + base) = v;
}

// ---------------- weight image packs (Wf1_p, Wp_{Q|AQ}, Wf1_a) ----------------
#define PW1 (768L * 96)      // Wf1_p A image
#define PW2 (1536L * 96)     // Wp B image (transpose gather)
#define PW3 (768L * 96)      // Wf1_a B image

__global__ __launch_bounds__(256)
void packw_k(const float* __restrict__ Wf1, const float* __restrict__ Wp)
{
    long gidx = (long)blockIdx.x * 256 + threadIdx.x;
    float v[8];
    if (gidx < PW1) {
        int c8 = (int)(gidx % 96);
        int m  = (int)(gidx / 96);
        int k0 = c8 * 8;
        const float* src = Wf1 + (long)m * 2 * DD + k0;
        float4 x = ((const float4*)src)[0], y = ((const float4*)src)[1];
        v[0]=x.x; v[1]=x.y; v[2]=x.z; v[3]=x.w; v[4]=y.x; v[5]=y.y; v[6]=y.z; v[7]=y.w;
        img_store(g_Wf1pI, m >> 7, m & 127, k0, pack8h(v));
    } else if (gidx < PW1 + PW2) {
        long idx = gidx - PW1;
        int c8 = (int)(idx % 96);
        int n  = (int)(idx / 96);
        int k0 = c8 * 8;
        #pragma unroll
        for (int i = 0; i < 8; i++)
            v[i] = Wp[(long)(k0 + i) * 3 * DD + DD + n];
        img_store(g_WpI, n >> 7, n & 127, k0, pack8h(v));
    } else {
        long idx = gidx - PW1 - PW2;
        if (idx >= PW3) return;
        int c8 = (int)(idx % 96);
        int n  = (int)(idx / 96);
        int k0 = c8 * 8;
        const float* src = Wf1 + (long)n * 2 * DD + DD + k0;
        float4 x = ((const float4*)src)[0], y = ((const float4*)src)[1];
        v[0]=x.x; v[1]=x.y; v[2]=x.z; v[3]=x.w; v[4]=y.x; v[5]=y.y; v[6]=y.z; v[7]=y.w;
        img_store(g_Wf1aI, n >> 7, n & 127, k0, pack8h(v));
    }
}

// ---------------- tmax image pack (640 rows/batch, 600 valid) -----------------
__global__ __launch_bounds__(256)
void packt_k()
{
    long gidx = (long)blockIdx.x * 256 + threadIdx.x;   // b*640*96 range
    int c8 = (int)(gidx % 96);
    long t  = gidx / 96;
    int r  = (int)(t % 640);
    int b  = (int)(t / 640);
    if (b >= BQ) return;
    int k0 = c8 * 8;
    float v[8];
    if (r < 600) {
        const float* src = g_tmax + ((long)b * 600 + r) * DD + k0;
        float4 x = ((const float4*)src)[0], y = ((const float4*)src)[1];
        v[0]=x.x; v[1]=x.y; v[2]=x.z; v[3]=x.w; v[4]=y.x; v[5]=y.y; v[6]=y.z; v[7]=y.w;
    } else {
        #pragma unroll
        for (int i = 0; i < 8; i++) v[i] = 0.f;
    }
    img_store(g_TmI + (long)b * 5 * NS64 * AT64, r >> 7, r & 127, k0, pack8h(v));
}

// ---------------- generic small HMMA GEMM (fp32 out, 128x128 CTA) -------------
// A image: mtile-major 128x64 tiles; B image: ntile-major 128x64 tiles.
__global__ __launch_bounds__(256, 2)
void hgemm_k(const unsigned char* __restrict__ Aimg, long a_bs,
             const unsigned char* __restrict__ Bimg, long b_bs,
             float* __restrict__ C, long c_ld, long c_bs, int M)
{
    extern __shared__ __align__(1024) unsigned char dsm[];
    __shared__ __align__(8) uint64_t s_full[2];
    __shared__ __align__(8) uint64_t s_emb[2];
    uint32_t dbase = smem_u32(dsm);
    uint32_t fb0   = smem_u32(&s_full[0]);
    uint32_t eb0   = smem_u32(&s_emb[0]);

    int tid  = threadIdx.x;
    int lane = tid & 31;
    int w    = tid >> 5;
    int mw   = w & 1;
    int nw   = w >> 1;
    int z    = blockIdx.z;
    int ntile = blockIdx.x;
    int mtile = blockIdx.y;

    const unsigned char* at = Aimg + (long)z * a_bs + (long)mtile * NS64 * AT64;
    const unsigned char* bt = Bimg + (long)z * b_bs + (long)ntile * NS64 * AT64;

    float acc[4][4][4];
    #pragma unroll
    for (int i = 0; i < 4; i++)
        #pragma unroll
        for (int j = 0; j < 4; j++)
            #pragma unroll
            for (int k = 0; k < 4; k++) acc[i][j][k] = 0.f;

    if (tid == 0) {
        #pragma unroll
        for (int s = 0; s < 2; s++) {
            mbar_init(fb0 + s * 8, 1);
            mbar_init(eb0 + s * 8, 256);
        }
    }
    asm volatile("fence.proxy.async.shared::cta;" ::: "memory");
    __syncthreads();

    if (tid == 0) {
        #pragma unroll
        for (int s = 0; s < 2; s++) {
            uint32_t mb = fb0 + s * 8;
            uint32_t sb = dbase + (uint32_t)s * STG2;
            mbar_expect(mb, STG2);
            bulkcp(sb,        at + (long)s * AT64, AT64, mb);
            bulkcp(sb + AT64, bt + (long)s * AT64, AT64, mb);
        }
    }

    for (int i = 0; i < NS64; i++) {
        int s = i & 1;
        mbar_wait(fb0 + s * 8, (i >> 1) & 1);
        uint32_t sb  = dbase + (uint32_t)s * STG2;
        uint32_t a_t = sb, b_t = sb + AT64;

        #pragma unroll
        for (int kk = 0; kk < 64; kk += 16) {
            uint32_t Bh[8];
            #pragma unroll
            for (int g = 0; g < 2; g++)
                ldm_x4(&Bh[g * 4], ldm_addr128(b_t, nw * 32 + g * 16, kk, lane));
            #pragma unroll
            for (int mf = 0; mf < 4; mf++) {
                uint32_t Ah[4];
                ldm_x4(Ah, ldm_addr128(a_t, mw * 64 + mf * 16, kk, lane));
                #pragma unroll
                for (int nf = 0; nf < 4; nf++) {
                    int g = nf >> 1, q = nf & 1;
                    mma16816(acc[mf][nf], Ah, Bh[g * 4 + q], Bh[g * 4 + 2 + q]);
                }
            }
        }
        mbar_arrive(eb0 + s * 8);
        if (tid == 0 && i + 2 < NS64) {
            mbar_wait(eb0 + s * 8, (i >> 1) & 1);
            int sl = i + 2;
            uint32_t mb = fb0 + s * 8;
            mbar_expect(mb, STG2);
            bulkcp(sb,        at + (long)sl * AT64, AT64, mb);
            bulkcp(sb + AT64, bt + (long)sl * AT64, AT64, mb);
        }
    }

    float* Cb = C + (long)z * c_bs;
    #pragma unroll
    for (int nf = 0; nf < 4; nf++) {
        int col = ntile * 128 + nw * 32 + nf * 8 + (lane & 3) * 2;
        #pragma unroll
        for (int mf = 0; mf < 4; mf++) {
            int r0 = mtile * 128 + mw * 64 + mf * 16 + (lane >> 2);
            int r1 = r0 + 8;
            float* acp = acc[mf][nf];
            if (r0 < M)
                *(float2*)(Cb + (long)r0 * c_ld + col) = make_float2(acp[0], acp[1]);
            if (r1 < M)
                *(float2*)(Cb + (long)r1 * c_ld + col) = make_float2(acp[2], acp[3]);
        }
    }
}

// Q -> SW128 fp16 tile image. thread = (b, mt, r, c8)
__global__ __launch_bounds__(256) void qsplit_k(const float* __restrict__ qps)
{
    long idx = (long)blockIdx.x * 256 + threadIdx.x;
    int c8 = (int)(idx % 96);
    long t  = idx / 96;
    int r  = (int)(t % 128);
    t /= 128;
    int mt = (int)(t % MT);
    int b  = (int)(t / MT);
    if (b >= BQ) return;
    int m = mt * 128 + r;
    int k0 = c8 * 8;
    float v[8];
    if (m < NTOT) {
        const float* src = qps + ((long)(b * NLYR + 1) * NTOT + m) * DD + k0;
        float4 a = ((const float4*)src)[0];
        float4 c = ((const float4*)src)[1];
        v[0]=a.x; v[1]=a.y; v[2]=a.z; v[3]=a.w; v[4]=c.x; v[5]=c.y; v[6]=c.z; v[7]=c.w;
    } else {
        #pragma unroll
        for (int i = 0; i < 8; i++) v[i] = 0.f;
    }
    uint4 hi = pack8h(v);
    int slab = k0 >> 6, kin = k0 & 63;
    uint32_t off = swz128((uint32_t)(r * 128 + kin * 2));
    long base = ((long)(b * MT + mt) * NS64 + slab) * AT64 + off;
    *(uint4*)(g_Qh + base) = hi;
}

// Wbig -> SW128 fp16 tile image. thread = (b, nt, r, c8)
__global__ __launch_bounds__(256) void wsplit_k(const float* __restrict__ ans,
                                                const float* __restrict__ Wt)
{
    long idx = (long)blockIdx.x * 256 + threadIdx.x;
    int c8 = (int)(idx % 96);
    long t  = idx / 96;
    int r  = (int)(t % 256);
    t /= 256;
    int nt = (int)(t % NT);
    int b  = (int)(t / NT);
    if (b >= BQ) return;
    int j = nt * 256 + r;
    int k0 = c8 * 8;
    const float* Av = ans + (long)(b * NLYR + 1) * DD + k0;
    float a[8], w1[8], w2[8];
    {
        float4 x = ((const float4*)Av)[0], y = ((const float4*)Av)[1];
        a[0]=x.x; a[1]=x.y; a[2]=x.z; a[3]=x.w; a[4]=y.x; a[5]=y.y; a[6]=y.z; a[7]=y.w;
    }
    if (j < DD) {
        const float* wr = Wt + (long)j * 3 * DD;
        float4 x = *(const float4*)(wr + DD + k0),     y = *(const float4*)(wr + DD + k0 + 4);
        float4 u = *(const float4*)(wr + 2 * DD + k0), w = *(const float4*)(wr + 2 * DD + k0 + 4);
        w1[0]=x.x; w1[1]=x.y; w1[2]=x.z; w1[3]=x.w; w1[4]=y.x; w1[5]=y.y; w1[6]=y.z; w1[7]=y.w;
        w2[0]=u.x; w2[1]=u.y; w2[2]=u.z; w2[3]=u.w; w2[4]=w.x; w2[5]=w.y; w2[6]=w.z; w2[7]=w.w;
    } else {
        int d = j - DD;
        const float* gr = g_G + (long)d * 2 * DD;
        float4 x = *(const float4*)(gr + k0),      y = *(const float4*)(gr + k0 + 4);
        float4 u = *(const float4*)(gr + DD + k0), w = *(const float4*)(gr + DD + k0 + 4);
        w1[0]=x.x; w1[1]=x.y; w1[2]=x.z; w1[3]=x.w; w1[4]=y.x; w1[5]=y.y; w1[6]=y.z; w1[7]=y.w;
        w2[0]=u.x; w2[1]=u.y; w2[2]=u.z; w2[3]=u.w; w2[4]=w.x; w2[5]=w.y; w2[6]=w.z; w2[7]=w.w;
    }
    float v[8];
    #pragma unroll
    for (int i = 0; i < 8; i++) v[i] = w1[i] + w2[i] * a[i];
    uint4 hi = pack8h(v);
    int slab = k0 >> 6, kin = k0 & 63;
    uint32_t off = swz128((uint32_t)(r * 128 + kin * 2));
    long base = ((long)(b * NT + nt) * NS64 + slab) * BT64 + off;
    *(uint4*)(g_Wh + base) = hi;
}

// ---------------- HMMA main GEMM: 128x128 CTA tile, 2 CTAs/SM (R13) ----------
__global__ __launch_bounds__(256, 2)
void tgemm_k(const float* __restrict__ bias, float* __restrict__ Y)
{
    extern __shared__ __align__(1024) unsigned char dsm[];
    __shared__ __align__(8) uint64_t s_full[2];
    __shared__ __align__(8) uint64_t s_emb[2];
    uint32_t dbase = smem_u32(dsm);
    uint32_t fb0   = smem_u32(&s_full[0]);
    uint32_t eb0   = smem_u32(&s_emb[0]);

    int tid  = threadIdx.x;
    int lane = tid & 31;
    int w    = tid >> 5;
    int mw   = w & 1;
    int nw   = w >> 1;
    int b    = blockIdx.z;
    int nt2  = blockIdx.x;
    int mt   = blockIdx.y;

    const unsigned char* qh = g_Qh + ((long)(b * MT + mt) * NS64) * AT64;
    const unsigned char* wh = g_Wh + ((long)(b * NT + (nt2 >> 1)) * NS64) * BT64
                                   + (long)(nt2 & 1) * HBT;

    float acc[4][4][4];
    #pragma unroll
    for (int i = 0; i < 4; i++)
        #pragma unroll
        for (int j = 0; j < 4; j++)
            #pragma unroll
            for (int k = 0; k < 4; k++) acc[i][j][k] = 0.f;

    if (tid == 0) {
        #pragma unroll
        for (int s = 0; s < 2; s++) {
            mbar_init(fb0 + s * 8, 1);
            mbar_init(eb0 + s * 8, 256);
        }
    }
    asm volatile("fence.proxy.async.shared::cta;" ::: "memory");
    __syncthreads();

    if (tid == 0) {
        #pragma unroll
        for (int s = 0; s < 2; s++) {
            uint32_t mb = fb0 + s * 8;
            uint32_t sb = dbase + (uint32_t)s * STG2;
            mbar_expect(mb, STG2);
            bulkcp(sb,         qh + (long)s * AT64, AT64, mb);
            bulkcp(sb + AT64,  wh + (long)s * BT64, HBT,  mb);
        }
    }

    for (int i = 0; i < NS64; i++) {
        int s = i & 1;
        mbar_wait(fb0 + s * 8, (i >> 1) & 1);

        uint32_t sb  = dbase + (uint32_t)s * STG2;
        uint32_t a_t = sb, b_t = sb + AT64;

        #pragma unroll
        for (int kk = 0; kk < 64; kk += 16) {
            uint32_t Bh[8];
            #pragma unroll
            for (int g = 0; g < 2; g++)
                ldm_x4(&Bh[g * 4], ldm_addr128(b_t, nw * 32 + g * 16, kk, lane));
            #pragma unroll
            for (int mf = 0; mf < 4; mf++) {
                uint32_t Ah[4];
                ldm_x4(Ah, ldm_addr128(a_t, mw * 64 + mf * 16, kk, lane));
                #pragma unroll
                for (int nf = 0; nf < 4; nf++) {
                    int g = nf >> 1, q = nf & 1;
                    mma16816(acc[mf][nf], Ah, Bh[g * 4 + q], Bh[g * 4 + 2 + q]);
                }
            }
        }
        mbar_arrive(eb0 + s * 8);

        if (tid == 0 && i + 2 < NS64) {
            mbar_wait(eb0 + s * 8, (i >> 1) & 1);
            int sl = i + 2;
            uint32_t mb = fb0 + s * 8;
            mbar_expect(mb, STG2);
            bulkcp(sb,        qh + (long)sl * AT64, AT64, mb);
            bulkcp(sb + AT64, wh + (long)sl * BT64, HBT,  mb);
        }
    }

    long yb = (long)b * NTOT * (2 * DD);
    #pragma unroll
    for (int nf = 0; nf < 4; nf++) {
        int col = nt2 * 128 + nw * 32 + nf * 8 + (lane & 3) * 2;
        float bv0 = bias[b * 2 * DD + col];
        float bv1 = bias[b * 2 * DD + col + 1];
        #pragma unroll
        for (int mf = 0; mf < 4; mf++) {
            int r0 = mt * 128 + mw * 64 + mf * 16 + (lane >> 2);
            int r1 = r0 + 8;
            float* acp = acc[mf][nf];
            if (r0 < NTOT)
                *(float2*)(Y + yb + (long)r0 * (2 * DD) + col) = make_float2(acp[0] + bv0, acp[1] + bv1);
            if (r1 < NTOT)
                *(float2*)(Y + yb + (long)r1 * (2 * DD) + col) = make_float2(acp[2] + bv0, acp[3] + bv1);
        }
    }
}

// ---------------- group max over passages by table id -----------------------
__global__ void tmax_k(const int* __restrict__ tids)
{
    int b   = blockIdx.x / NTOK;
    int tok = blockIdx.x % NTOK;
    int d   = threadIdx.x;
    __shared__ int ids[NP];
    if (threadIdx.x < NP) ids[threadIdx.x] = tids[b * NP + threadIdx.x];
    float m[NTAB];
    #pragma unroll
    for (int t = 0; t < NTAB; t++) m[t] = -3.0e38f;
    __syncthreads();
    const float* Yb = g_Y + (long)b * NTOT * 2 * DD;
    for (int p = 0; p < NP; p++) {
        float v = Yb[(long)(p * NTOK + tok) * 2 * DD + d];
        int id = ids[p];
        #pragma unroll
        for (int t = 0; t < NTAB; t++)
            if (id == t) m[t] = fmaxf(m[t], v);
    }
    #pragma unroll
    for (int t = 0; t < NTAB; t++)
        g_tmax[(((long)b * NTAB + t) * NTOK + tok) * DD + d] = m[t];
}

// ---------------- final -----------------------------------------------------
__global__ void final_k(const float* __restrict__ masks, const int* __restrict__ tids,
                        const float* __restrict__ Wf2, const float* __restrict__ bf2,
                        float* __restrict__ out)
{
    int b = blockIdx.x / NP, p = blockIdx.x % NP;
    int tbl = tids[b * NP + p];
    __shared__ float w2[DD];
    __shared__ float ms[NTOK];
    __shared__ float red[256];
    for (int i = threadIdx.x; i < DD; i += blockDim.x) w2[i] = Wf2[i];
    if (threadIdx.x < NTOK) ms[threadIdx.x] = masks[(b * NP + p) * NTOK + threadIdx.x];
    __syncthreads();

    const float* p1 = g_Y + ((long)b * NTOT + (long)p * NTOK) * 2 * DD + DD;
    const float* p2 = g_p2 + ((long)b * NTAB + tbl) * NTOK * DD;
    float acc = 0.f;
    for (int tok = 0; tok < NTOK; tok++) {
        float m = ms[tok];
        const float* r1 = p1 + (long)tok * 2 * DD;
        const float* r2 = p2 + tok * DD;
        #pragma unroll 3
        for (int d = threadIdx.x; d < DD; d += 256) {
            float v = r1[d] + r2[d];
            acc += m * w2[d] * fmaxf(v, 0.f);
        }
    }
    red[threadIdx.x] = acc;
    __syncthreads();
    for (int s = 128; s > 0; s >>= 1) {
        if (threadIdx.x < s) red[threadIdx.x] += red[threadIdx.x + s];
        __syncthreads();
    }
    if (threadIdx.x == 0) {
        float msum = 0.f;
        for (int t = 0; t < NTOK; t++) msum += ms[t];
        out[b * NP + p] = red[0] + bf2[0] * msum;
    }
}

// ---------------- launcher --------------------------------------------------
extern "C" void kernel_launch(void* const* d_in, const int* in_sizes, int n_in,
                              void* d_out, int out_size)
{
    const float* ans   = (const float*)d_in[0];
    const float* qps   = (const float*)d_in[1];
    const float* masks = (const float*)d_in[2];
    const int*   tids  = (const int*)  d_in[3];
    const float* Wp    = (const float*)d_in[4];
    const float* bp    = (const float*)d_in[5];
    const float* Wt    = (const float*)d_in[6];
    const float* bt    = (const float*)d_in[7];
    const float* Wf1   = (const float*)d_in[8];
    const float* bf1   = (const float*)d_in[9];
    const float* Wf2   = (const float*)d_in[10];
    const float* bf2   = (const float*)d_in[11];
    float* out = (float*)d_out;

    void *pG, *pBias, *pY, *pP2;
    void *pWf1pI, *pWpI, *pWf1aI, *pTmI;
    cudaGetSymbolAddress(&pG,     g_G);
    cudaGetSymbolAddress(&pBias,  g_bias);
    cudaGetSymbolAddress(&pY,     g_Y);
    cudaGetSymbolAddress(&pP2,    g_p2);
    cudaGetSymbolAddress(&pWf1pI, g_Wf1pI);
    cudaGetSymbolAddress(&pWpI,   g_WpI);
    cudaGetSymbolAddress(&pWf1aI, g_Wf1aI);
    cudaGetSymbolAddress(&pTmI,   g_TmI);

    int dyn2 = 2 * STG2;   // 64KB
    cudaFuncSetAttribute(hgemm_k, cudaFuncAttributeMaxDynamicSharedMemorySize, dyn2);
    cudaFuncSetAttribute(tgemm_k, cudaFuncAttributeMaxDynamicSharedMemorySize, dyn2);

    // launch 0,1: prep (c_t, u)
    prep1_k<<<dim3(96, BQ), 256>>>(ans, Wp, bp, Wt, bt);
    prep_u_k<<<dim3(96, BQ), 256>>>(Wf1, bf1);

    // launch 2: pack weight images (Wf1_p, Wp, Wf1_a)
    {
        long tot = PW1 + PW2 + PW3;
        packw_k<<<(unsigned)((tot + 255) / 256), 256>>>(Wf1, Wp);
    }

    // launch 3: G = Wf1_p @ Wp^T on tensor cores  <-- ncu capture window
    hgemm_k<<<dim3(12, 6, 1), 256, dyn2>>>(
        (const unsigned char*)pWf1pI, 0,
        (const unsigned char*)pWpI,   0,
        (float*)pG, 2 * DD, 0, DD);

    // launch 4: Q image prepack
    {
        long tq = (long)BQ * MT * 128 * 96;
        qsplit_k<<<(unsigned)((tq + 255) / 256), 256>>>(qps);
    }

    // launch 5: W image prepack (needs G)
    {
        long tw = (long)BQ * NT * 256 * 96;
        wsplit_k<<<(unsigned)((tw + 255) / 256), 256>>>(ans, Wt);
    }

    // launch 6: main tensor GEMM
    tgemm_k<<<dim3(NT2, MT, BQ), 256, dyn2>>>((const float*)pBias, (float*)pY);

    // launch 7: table group-max
    tmax_k<<<BQ * NTOK, DD>>>(tids);

    // launch 8: pack tmax image
    {
        long tt = (long)BQ * 640 * 96;
        packt_k<<<(unsigned)((tt + 255) / 256), 256>>>();
    }

    // launch 9: part2 = tmax @ Wf1_a^T on tensor cores
    hgemm_k<<<dim3(6, 5, BQ), 256, dyn2>>>(
        (const unsigned char*)pTmI, (long)5 * NS64 * AT64,
        (const unsigned char*)pWf1aI, 0,
        (float*)pP2, DD, (long)NTAB * NTOK * DD, NTAB * NTOK);

    // launch 10: final masked reduction
    final_k<<<BQ * NP, 256>>>(masks, tids, Wf2, bf2, out);
}